// round 6
// baseline (speedup 1.0000x reference)
#include <cuda_runtime.h>
#include <mma.h>

using namespace nvcuda;

namespace {
constexpr int TB    = 512;   // 16 warps
constexpr int MROWS = 32;    // batch rows per block
constexpr int HD    = 128;
constexpr int DD    = 64;
constexpr int TT    = 100;
constexpr int BB    = 4096;
constexpr int LD    = 132;   // state tiles ld
constexpr int LDW   = 132;   // W1T/W2T ld
constexpr int LDX   = 68;    // x tile ld
constexpr int BSTRIDE = 520; // bias array stride (col-major ldb=4, reach 4*127+7=515)

constexpr int SM_FLOATS = 2*128*LDW + 3*MROWS*LD + MROWS*LDX + 128 + 8*BSTRIDE + 8;
constexpr int SMEM_BYTES = SM_FLOATS * 4;   // ~211.7 KB
}

using FragAcc = wmma::fragment<wmma::accumulator, 16, 16, 8, float>;
using FragA   = wmma::fragment<wmma::matrix_a, 16, 16, 8, wmma::precision::tf32, wmma::row_major>;
using FragB   = wmma::fragment<wmma::matrix_b, 16, 16, 8, wmma::precision::tf32, wmma::row_major>;
using FragBc  = wmma::fragment<wmma::matrix_b, 16, 16, 8, wmma::precision::tf32, wmma::col_major>;

__device__ __forceinline__ float tanh_fast(float x) {
    float e = __expf(2.0f * x);
    return 1.0f - 2.0f / (e + 1.0f);
}
__device__ __forceinline__ float sigm_fast(float x) {
    return 1.0f / (1.0f + __expf(-x));
}

// acc += 1-col ones @ bias-row  (adds bias[n] to every row; lanes k>0 hit zeros in A)
__device__ __forceinline__ void bias_mma(FragAcc& acc, const float* __restrict__ sOnes,
                                         const float* __restrict__ biasArr, int c0)
{
    FragA ones;
    wmma::load_matrix_sync(ones, sOnes, 8);
    FragBc bb;
    wmma::load_matrix_sync(bb, biasArr + 4 * c0, 4);
    wmma::mma_sync(acc, ones, bb, acc);
}

// ODE GEMM: acc += A[r0:,0:128] @ Bsh[:, c0:c0+16]; A pre-rounded tf32 (NO cvts).
__device__ __forceinline__ void gemm_ode16(FragAcc& acc, const float* __restrict__ A,
                                           const float* __restrict__ Bsh, int r0, int c0)
{
#pragma unroll
    for (int k0 = 0; k0 < 128; k0 += 8) {
        FragA a;
        wmma::load_matrix_sync(a, A + r0 * LD + k0, LD);
        FragB b;
        wmma::load_matrix_sync(b, Bsh + k0 * LDW + c0, LDW);
        wmma::mma_sync(acc, a, b, acc);
    }
}

// 3-term hi/lo tf32 split segment: acc += A[r0:,0:K] @ Bg^T[:, c0:c0+16]
template <int K>
__device__ __forceinline__ void split_seg(FragAcc& acc, const float* __restrict__ A, int lda,
                                          const float* __restrict__ Bg, int r0, int c0)
{
#pragma unroll
    for (int k0 = 0; k0 < K; k0 += 8) {
        FragA ah, al;
        wmma::load_matrix_sync(ah, A + r0 * lda + k0, lda);
#pragma unroll
        for (int i = 0; i < ah.num_elements; i++) {
            float v  = ah.x[i];
            float vh = wmma::__float_to_tf32(v);
            ah.x[i] = vh;
            al.x[i] = wmma::__float_to_tf32(v - vh);
        }
        FragBc bh, bl;
        wmma::load_matrix_sync(bh, Bg + (size_t)c0 * K + k0, K);
#pragma unroll
        for (int i = 0; i < bh.num_elements; i++) {
            float v = bh.x[i];
            float h = wmma::__float_to_tf32(v);
            bh.x[i] = h;
            bl.x[i] = wmma::__float_to_tf32(v - h);
        }
        wmma::mma_sync(acc, ah, bh, acc);
        wmma::mma_sync(acc, al, bh, acc);
        wmma::mma_sync(acc, ah, bl, acc);
    }
}

// Fused split GEMM + bias, result stored to Cdst tile (smem or global).
template <int K1, int K2>
__device__ __noinline__ void split_gemm_store(
    const float* __restrict__ A1, int lda1, const float* __restrict__ B1,
    const float* __restrict__ A2, int lda2, const float* __restrict__ B2,
    const float* __restrict__ biasArr, const float* __restrict__ sOnes,
    float* __restrict__ Cdst, int ldc, int r0, int c0)
{
    FragAcc acc;
    wmma::fill_fragment(acc, 0.0f);
    split_seg<K1>(acc, A1, lda1, B1, r0, c0);
    if constexpr (K2 > 0) split_seg<K2>(acc, A2, lda2, B2, r0, c0);
    bias_mma(acc, sOnes, biasArr, c0);
    wmma::store_matrix_sync(Cdst + (size_t)r0 * ldc + c0, acc, ldc, wmma::mem_row_major);
}

__global__ void __launch_bounds__(TB, 1)
odernn_kernel(const float* __restrict__ x_seq, const float* __restrict__ t_seq,
              const float* __restrict__ W1,   const float* __restrict__ b1,
              const float* __restrict__ W2,   const float* __restrict__ b2,
              const float* __restrict__ W_ih, const float* __restrict__ W_hh,
              const float* __restrict__ b_ih, const float* __restrict__ b_hh,
              const float* __restrict__ W_mu, const float* __restrict__ b_mu,
              const float* __restrict__ W_lv, const float* __restrict__ b_lv,
              float* __restrict__ out)
{
    extern __shared__ float sm[];
    float* sW1T  = sm;                    // 128*LDW (tf32, k-major, n across)
    float* sW2T  = sW1T + 128 * LDW;
    float* sH    = sW2T + 128 * LDW;      // fp32 h
    float* sTmp  = sH   + MROWS * LD;     // tf32-rounded ODE state
    float* sU    = sTmp + MROWS * LD;     // scratch / tanh intermediate
    float* sX    = sU   + MROWS * LD;
    float* sOnes = sX   + MROWS * LDX;    // 16x8, col0 = 1
    float* sB1   = sOnes + 128;           // bias arrays: value at [4*n]
    float* sB2   = sB1  + BSTRIDE;
    float* sBr   = sB2  + BSTRIDE;
    float* sBz   = sBr  + BSTRIDE;
    float* sBin  = sBz  + BSTRIDE;
    float* sBhn  = sBin + BSTRIDE;
    float* sBmu  = sBhn + BSTRIDE;
    float* sBlv  = sBmu + BSTRIDE;
    float* sSub  = sBlv + BSTRIDE;

    const int tid  = threadIdx.x;
    const int warp = tid >> 5;
    const int r0   = (warp & 1) * 16;
    const int c0   = (warp >> 1) * 16;
    const int m0   = blockIdx.x * MROWS;

    // ---- init: zero ones+bias region, state; stage weights tf32 k-major ----
    for (int i = tid; i < 128 + 8 * BSTRIDE; i += TB) sOnes[i] = 0.0f;
    for (int i = tid; i < MROWS * LD; i += TB) { sH[i] = 0.0f; sTmp[i] = 0.0f; }
    for (int i = tid; i < 128 * 128; i += TB) {
        int n = i >> 7, k = i & 127;
        sW1T[k * LDW + n] = wmma::__float_to_tf32(W1[i]);
        sW2T[k * LDW + n] = wmma::__float_to_tf32(W2[i]);
    }
    __syncthreads();
    for (int i = tid; i < 128; i += TB) {
        if (i < 16) sOnes[i * 8] = 1.0f;
        sB1 [4 * i] = wmma::__float_to_tf32(b1[i]);
        sB2 [4 * i] = wmma::__float_to_tf32(b2[i]);
        sBr [4 * i] = wmma::__float_to_tf32(b_ih[i]       + b_hh[i]);
        sBz [4 * i] = wmma::__float_to_tf32(b_ih[128 + i] + b_hh[128 + i]);
        sBin[4 * i] = wmma::__float_to_tf32(b_ih[256 + i]);
        sBhn[4 * i] = wmma::__float_to_tf32(b_hh[256 + i]);
        sBmu[4 * i] = wmma::__float_to_tf32(b_mu[i]);
        sBlv[4 * i] = wmma::__float_to_tf32(b_lv[i]);
    }
    __syncthreads();

#pragma unroll 1
    for (int t = 0; t < TT; t++) {
        if (tid == 0)
            sSub[0] = (t == 0) ? 0.0f : (t_seq[t] - t_seq[t - 1]) * 0.25f;
        for (int j = tid; j < MROWS * DD; j += TB) {
            int m = j >> 6, d = j & 63;
            sX[m * LDX + d] = x_seq[((size_t)(m0 + m) * TT + t) * DD + d];
        }
        __syncthreads();
        const float sub = sSub[0];

        if (t > 0) {
#pragma unroll 1
            for (int s = 0; s < 4; s++) {
                FragAcc racc;
                wmma::fill_fragment(racc, 0.0f);
#pragma unroll 1
                for (int p = 0; p < 4; p++) {
                    // U = tanh(Tmp @ W1T + b1), rounded to tf32, stored
                    FragAcc u;
                    wmma::fill_fragment(u, 0.0f);
                    gemm_ode16(u, sTmp, sW1T, r0, c0);
                    bias_mma(u, sOnes, sB1, c0);
#pragma unroll
                    for (int i = 0; i < u.num_elements; i++)
                        u.x[i] = wmma::__float_to_tf32(tanh_fast(u.x[i]));
                    wmma::store_matrix_sync(sU + r0 * LD + c0, u, LD, wmma::mem_row_major);
                    __syncthreads();
                    // k = U @ W2T + b2
                    FragAcc kk;
                    wmma::fill_fragment(kk, 0.0f);
                    gemm_ode16(kk, sU, sW2T, r0, c0);
                    bias_mma(kk, sOnes, sB2, c0);
                    // RK4 combine, in registers
                    const float coef = (p == 0 || p == 3) ? 1.0f : 2.0f;
#pragma unroll
                    for (int i = 0; i < kk.num_elements; i++) racc.x[i] += coef * kk.x[i];
                    FragAcc hh;
                    wmma::load_matrix_sync(hh, sH + r0 * LD + c0, LD, wmma::mem_row_major);
                    if (p < 3) {
                        const float cs = (p == 2) ? sub : 0.5f * sub;
#pragma unroll
                        for (int i = 0; i < kk.num_elements; i++)
                            kk.x[i] = wmma::__float_to_tf32(hh.x[i] + cs * kk.x[i]);
                        wmma::store_matrix_sync(sTmp + r0 * LD + c0, kk, LD, wmma::mem_row_major);
                    } else {
#pragma unroll
                        for (int i = 0; i < hh.num_elements; i++)
                            hh.x[i] += (sub * (1.0f / 6.0f)) * racc.x[i];
                        wmma::store_matrix_sync(sH + r0 * LD + c0, hh, LD, wmma::mem_row_major);
#pragma unroll
                        for (int i = 0; i < hh.num_elements; i++)
                            hh.x[i] = wmma::__float_to_tf32(hh.x[i]);
                        wmma::store_matrix_sync(sTmp + r0 * LD + c0, hh, LD, wmma::mem_row_major);
                    }
                    __syncthreads();
                }
            }
        }

        // ---- GRU (gates in registers; no internal barriers) ----
        // r = sigm(x@Wir^T + h@Whr^T + br)
        split_gemm_store<64, 128>(sX, LDX, W_ih, sH, LD, W_hh,
                                  sBr, sOnes, sU, LD, r0, c0);
        FragAcc fr;
        wmma::load_matrix_sync(fr, sU + r0 * LD + c0, LD, wmma::mem_row_major);
#pragma unroll
        for (int i = 0; i < fr.num_elements; i++) fr.x[i] = sigm_fast(fr.x[i]);
        // i_n, h_n
        split_gemm_store<64, 0>(sX, LDX, W_ih + (size_t)256 * 64, nullptr, 0, nullptr,
                                sBin, sOnes, sTmp, LD, r0, c0);
        split_gemm_store<128, 0>(sH, LD, W_hh + (size_t)256 * 128, nullptr, 0, nullptr,
                                 sBhn, sOnes, sU, LD, r0, c0);
        FragAcc fhn, fin;
        wmma::load_matrix_sync(fhn, sU  + r0 * LD + c0, LD, wmma::mem_row_major);
        wmma::load_matrix_sync(fin, sTmp + r0 * LD + c0, LD, wmma::mem_row_major);
#pragma unroll
        for (int i = 0; i < fr.num_elements; i++)
            fr.x[i] = tanh_fast(fin.x[i] + fr.x[i] * fhn.x[i]);   // n stored in fr
        // z
        split_gemm_store<64, 128>(sX, LDX, W_ih + (size_t)128 * 64, sH, LD,
                                  W_hh + (size_t)128 * 128, sBz, sOnes, sU, LD, r0, c0);
        FragAcc fz;
        wmma::load_matrix_sync(fz, sU + r0 * LD + c0, LD, wmma::mem_row_major);
        __syncthreads();   // all warps done READING sH before it is rewritten
        FragAcc hh;
        wmma::load_matrix_sync(hh, sH + r0 * LD + c0, LD, wmma::mem_row_major);
#pragma unroll
        for (int i = 0; i < hh.num_elements; i++) {
            float z = sigm_fast(fz.x[i]);
            hh.x[i] = (1.0f - z) * fr.x[i] + z * hh.x[i];
        }
        wmma::store_matrix_sync(sH + r0 * LD + c0, hh, LD, wmma::mem_row_major);
#pragma unroll
        for (int i = 0; i < hh.num_elements; i++)
            hh.x[i] = wmma::__float_to_tf32(hh.x[i]);
        wmma::store_matrix_sync(sTmp + r0 * LD + c0, hh, LD, wmma::mem_row_major);
        __syncthreads();
    }

    // ---- outputs straight to global ----
    split_gemm_store<128, 0>(sH, LD, W_mu, nullptr, 0, nullptr,
                             sBmu, sOnes, out + (size_t)m0 * HD, HD, r0, c0);
    split_gemm_store<128, 0>(sH, LD, W_lv, nullptr, 0, nullptr,
                             sBlv, sOnes, out + (size_t)BB * HD + (size_t)m0 * HD, HD, r0, c0);
}

extern "C" void kernel_launch(void* const* d_in, const int* in_sizes, int n_in,
                              void* d_out, int out_size)
{
    (void)in_sizes; (void)n_in; (void)out_size;
    static bool attr_done = false;
    if (!attr_done) {
        cudaFuncSetAttribute(odernn_kernel,
                             cudaFuncAttributeMaxDynamicSharedMemorySize, SMEM_BYTES);
        attr_done = true;
    }
    odernn_kernel<<<BB / MROWS, TB, SMEM_BYTES>>>(
        (const float*)d_in[0],  (const float*)d_in[1],
        (const float*)d_in[2],  (const float*)d_in[3],
        (const float*)d_in[4],  (const float*)d_in[5],
        (const float*)d_in[6],  (const float*)d_in[7],
        (const float*)d_in[8],  (const float*)d_in[9],
        (const float*)d_in[10], (const float*)d_in[11],
        (const float*)d_in[12], (const float*)d_in[13],
        (float*)d_out);
}